// round 7
// baseline (speedup 1.0000x reference)
#include <cuda_runtime.h>
#include <cuda_bf16.h>
#include <math.h>
#include <stdint.h>

// ---------------------------------------------------------------------------
// Problem constants
// ---------------------------------------------------------------------------
#define B_ 32768
#define D_ 256
#define N_ 8192

#define MT 128              // M rows per CTA
#define NTILE 128           // N cols per B stream block
#define NTILES (N_ / NTILE) // 64
#define MTILES (B_ / MT)    // 256
#define KST 5               // B smem ring stages

#define BLK 16384           // one k64 block: 128 rows x 64 bf16 (SW128-swizzled)

// dynamic smem layout
#define SM_AFULL  8
#define SM_KFULL  16        // 5 x 8B (16..55)
#define SM_KEMPTY 56        // 5 x 8B (56..95)
#define SM_SV4V   128       // uint4[128][2] values  (4KB)
#define SM_SV4I   4224      // uint4[128][2] indices (4KB)
#define SM_A      8448      // 8 x 16KB = 128KB (hi0-3, lo0-3)
#define SM_B      (SM_A + 8 * BLK)       // 139520
#define SMEM_TOTAL (SM_B + KST * BLK)    // 221440

#define EPI_BLOCKS (B_ / 8)

// ---------------------------------------------------------------------------
// Global scratch
// ---------------------------------------------------------------------------
__device__ __align__(16) uint8_t g_Asw[(size_t)MTILES * 8 * BLK];  // 32 MB
__device__ __align__(16) uint8_t g_Bsw[(size_t)NTILES * 4 * BLK];  // 4 MB (hi only)
__device__ int4  g_top4[B_];
__device__ float g_partial[EPI_BLOCKS];

// ---------------------------------------------------------------------------
// PTX helpers (family-wide features only — NO tcgen05 at compute_103)
// ---------------------------------------------------------------------------
__device__ __forceinline__ uint32_t smem_u32(const void* p) {
    uint32_t a;
    asm("{ .reg .u64 t; cvta.to.shared.u64 t, %1; cvt.u32.u64 %0, t; }"
        : "=r"(a) : "l"(p));
    return a;
}
__device__ __forceinline__ uint32_t elect_one() {
    uint32_t pred;
    asm volatile("{\n\t.reg .pred p;\n\telect.sync _|p, 0xFFFFFFFF;\n\t"
                 "selp.b32 %0, 1, 0, p;\n\t}" : "=r"(pred));
    return pred;
}
#define MBAR_INIT(addr, cnt) \
    asm volatile("mbarrier.init.shared.b64 [%0], %1;" :: "r"(addr), "r"(cnt) : "memory")
#define MBAR_EXPECT_TX(addr, bytes) \
    asm volatile("mbarrier.arrive.expect_tx.shared.b64 _, [%0], %1;" \
                 :: "r"(addr), "r"(bytes) : "memory")
#define MBAR_ARRIVE(addr) \
    asm volatile("mbarrier.arrive.shared.b64 _, [%0];" :: "r"(addr) : "memory")
#define MBAR_WAIT(addr, ph) do {                                              \
    uint32_t _m = (addr), _p = (ph), _d;                                      \
    asm volatile("{\n\t.reg .pred p;\n\t"                                     \
        "mbarrier.try_wait.parity.acquire.cta.shared::cta.b64 p, [%1], %2;\n\t" \
        "selp.b32 %0, 1, 0, p;\n\t}" : "=r"(_d) : "r"(_m), "r"(_p) : "memory");\
    if (!_d) {                                                                \
        asm volatile("{\n\t.reg .pred P1;\n\t"                                \
            "WL_%=:\n\t"                                                      \
            "mbarrier.try_wait.parity.acquire.cta.shared::cta.b64 P1, [%0], %1, 0x989680;\n\t" \
            "@P1 bra.uni WD_%=;\n\t"                                          \
            "bra.uni WL_%=;\n\t"                                              \
            "WD_%=:\n\t}" :: "r"(_m), "r"(_p) : "memory");                    \
    } } while (0)
#define BULK_G2S(dst, src, bytes, mbar) \
    asm volatile("cp.async.bulk.shared::cta.global.mbarrier::complete_tx::bytes " \
                 "[%0], [%1], %2, [%3];" \
                 :: "r"(dst), "l"(src), "r"(bytes), "r"(mbar) : "memory")
#define LDSM_X4(r0, r1, r2, r3, a) \
    asm volatile("ldmatrix.sync.aligned.m8n8.x4.shared.b16 {%0,%1,%2,%3}, [%4];" \
        : "=r"(r0), "=r"(r1), "=r"(r2), "=r"(r3) : "r"(a))
#define MMA_BF16(d, a0, a1, a2, a3, b0, b1) \
    asm volatile("mma.sync.aligned.m16n8k16.row.col.f32.bf16.bf16.f32 " \
        "{%0,%1,%2,%3}, {%4,%5,%6,%7}, {%8,%9}, {%0,%1,%2,%3};" \
        : "+f"((d)[0]), "+f"((d)[1]), "+f"((d)[2]), "+f"((d)[3]) \
        : "r"(a0), "r"(a1), "r"(a2), "r"(a3), "r"(b0), "r"(b1))

union Pack8 { __nv_bfloat16 h[8]; uint4 v; };

__device__ __forceinline__ bool better(float v, int i, float w, int k) {
    return v > w || (v == w && i < k);
}
// Insert (v,n) into desc-sorted top-4 list.
__device__ __forceinline__ void ins4(float v, int n, float tv[4], int ti[4]) {
    if (!better(v, n, tv[3], ti[3])) return;
    if (better(v, n, tv[0], ti[0])) {
        tv[3]=tv[2]; ti[3]=ti[2]; tv[2]=tv[1]; ti[2]=ti[1];
        tv[1]=tv[0]; ti[1]=ti[0]; tv[0]=v; ti[0]=n;
    } else if (better(v, n, tv[1], ti[1])) {
        tv[3]=tv[2]; ti[3]=ti[2]; tv[2]=tv[1]; ti[2]=ti[1]; tv[1]=v; ti[1]=n;
    } else if (better(v, n, tv[2], ti[2])) {
        tv[3]=tv[2]; ti[3]=ti[2]; tv[2]=v; ti[2]=n;
    } else { tv[3]=v; ti[3]=n; }
}

// ---------------------------------------------------------------------------
// Kernel 1: split X into bf16 hi/lo, pre-swizzled SW128 16KB blocks.
// ---------------------------------------------------------------------------
__global__ void split_x_kernel(const float* __restrict__ X) {
    int g = blockIdx.x * 256 + threadIdx.x;
    int b  = g >> 5;
    int cg = g & 31;
    const float4* xp = (const float4*)(X + (size_t)b * D_ + cg * 8);
    float4 x0 = xp[0], x1 = xp[1];
    float xs[8] = {x0.x, x0.y, x0.z, x0.w, x1.x, x1.y, x1.z, x1.w};
    Pack8 hi, lo;
    #pragma unroll
    for (int i = 0; i < 8; i++) {
        __nv_bfloat16 h = __float2bfloat16(xs[i]);
        hi.h[i] = h;
        lo.h[i] = __float2bfloat16(xs[i] - __bfloat162float(h));
    }
    int mtile = b >> 7, m = b & 127, kc = cg >> 3;
    uint32_t off = m * 128 + (cg & 7) * 16;
    uint32_t sw = off ^ ((off >> 3) & 0x70);
    *(uint4*)(g_Asw + ((size_t)(mtile * 8 + kc)) * BLK + sw) = hi.v;
    *(uint4*)(g_Asw + ((size_t)(mtile * 8 + 4 + kc)) * BLK + sw) = lo.v;
}

// ---------------------------------------------------------------------------
// Kernel 2: normalize codebook rows, bf16 hi only, pre-swizzled blocks.
// Block (ntile*4 + kc); 128 n-rows x 64 bf16 each.
// ---------------------------------------------------------------------------
__global__ void split_cb_kernel(const float* __restrict__ E) {
    int n = blockIdx.x;
    int t = threadIdx.x;
    float v = E[(size_t)n * D_ + t];
    float s = v * v;
    #pragma unroll
    for (int o = 16; o; o >>= 1) s += __shfl_xor_sync(0xffffffffu, s, o);
    __shared__ float red[8];
    __shared__ float sv[256];
    if ((t & 31) == 0) red[t >> 5] = s;
    __syncthreads();
    if (t == 0) {
        float tot = 0.f;
        #pragma unroll
        for (int i = 0; i < 8; i++) tot += red[i];
        red[0] = fmaxf(sqrtf(tot), 1e-12f);
    }
    __syncthreads();
    sv[t] = v / red[0];
    __syncthreads();
    if (t < 32) {
        int cg = t;
        Pack8 u;
        #pragma unroll
        for (int i = 0; i < 8; i++) u.h[i] = __float2bfloat16(sv[cg * 8 + i]);
        int nc = n >> 7, r = n & 127, kc = cg >> 3;
        uint32_t off = r * 128 + (cg & 7) * 16;
        uint32_t sw = off ^ ((off >> 3) & 0x70);
        *(uint4*)(g_Bsw + ((size_t)(nc * 4 + kc)) * BLK + sw) = u.v;
    }
}

// ---------------------------------------------------------------------------
// Kernel 3: HMMA GEMM (2 terms: hi_x.hi_e + lo_x.hi_e) + per-row top-4.
// 288 threads: warps 0-7 compute (4x2 grid, 32x64 tiles); warp 8 produces.
// ---------------------------------------------------------------------------
__global__ __launch_bounds__(288, 1) void mma_argmax_kernel() {
    extern __shared__ char smem[];
    const uint32_t sb = smem_u32(smem);
    uint4* sv4v = (uint4*)(smem + SM_SV4V);
    uint4* sv4i = (uint4*)(smem + SM_SV4I);
    const int tid = threadIdx.x, wid = tid >> 5, lane = tid & 31;

    if (tid == 0) {
        MBAR_INIT(sb + SM_AFULL, 1);
        #pragma unroll
        for (int s = 0; s < KST; s++) {
            MBAR_INIT(sb + SM_KFULL + 8 * s, 1);
            MBAR_INIT(sb + SM_KEMPTY + 8 * s, 8);
        }
        asm volatile("fence.proxy.async.shared::cta;" ::: "memory");
    }
    __syncthreads();

    if (wid == 8) {
        // ---- producer: A once (8 x 16KB), then B hi ring (4 blocks / tile) ----
        if (elect_one()) {
            MBAR_EXPECT_TX(sb + SM_AFULL, 8 * BLK);
            #pragma unroll
            for (int blk = 0; blk < 8; blk++)
                BULK_G2S(sb + SM_A + blk * BLK,
                         g_Asw + ((size_t)blockIdx.x * 8 + blk) * BLK,
                         BLK, sb + SM_AFULL);
            int ks = 0, kph = 1;
            for (int c = 0; c < NTILES; c++) {
                for (int t = 0; t < 4; t++) {
                    MBAR_WAIT(sb + SM_KEMPTY + 8 * ks, kph);
                    MBAR_EXPECT_TX(sb + SM_KFULL + 8 * ks, BLK);
                    BULK_G2S(sb + SM_B + ks * BLK,
                             g_Bsw + ((size_t)c * 4 + t) * BLK,
                             BLK, sb + SM_KFULL + 8 * ks);
                    if (++ks == KST) { ks = 0; kph ^= 1; }
                }
            }
        }
    } else {
        // ---- compute warps ----
        const int wm = wid >> 1, wn = wid & 1;
        const int sx = (lane & 7) * 16;
        const int a_row0 = lane & 15;
        const int a_kbh = (lane >> 4) * 16;
        const int b_rowoff = ((lane >> 4) & 1) * 8 + (lane & 7);
        const int b_kbh = ((lane >> 3) & 1) * 16;
        const uint32_t aWarp = sb + SM_A + wm * 4096 + a_row0 * 128;
        const int g = lane >> 2, cq = lane & 3;

        float tv[4][4];
        int   ti[4][4];
        #pragma unroll
        for (int s = 0; s < 4; s++)
            #pragma unroll
            for (int r = 0; r < 4; r++) { tv[s][r] = -3.4e38f; ti[s][r] = 0x7fffffff; }

        MBAR_WAIT(sb + SM_AFULL, 0);

        int ks = 0, kph = 0;
        for (int c = 0; c < NTILES; c++) {
            float acc[2][8][4];
            #pragma unroll
            for (int mt = 0; mt < 2; mt++)
                #pragma unroll
                for (int nt = 0; nt < 8; nt++)
                    #pragma unroll
                    for (int r = 0; r < 4; r++) acc[mt][nt][r] = 0.f;

            #pragma unroll 1
            for (int j = 0; j < 4; j++) {     // B hi_j against A hi_j and lo_j
                MBAR_WAIT(sb + SM_KFULL + 8 * ks, kph);
                const uint32_t bBase = sb + SM_B + ks * BLK + wn * 8192;
                #pragma unroll
                for (int q = 0; q < 4; q++) {
                    uint32_t bb[4][4];
                    #pragma unroll
                    for (int p = 0; p < 4; p++) {
                        uint32_t bAddr = bBase + (p * 16 + b_rowoff) * 128
                                       + ((q * 32 + b_kbh) ^ sx);
                        LDSM_X4(bb[p][0], bb[p][1], bb[p][2], bb[p][3], bAddr);
                    }
                    uint32_t a0h[4], a1h[4], a0l[4], a1l[4];
                    uint32_t aAddr = aWarp + j * BLK + ((q * 32 + a_kbh) ^ sx);
                    LDSM_X4(a0h[0], a0h[1], a0h[2], a0h[3], aAddr);
                    LDSM_X4(a1h[0], a1h[1], a1h[2], a1h[3], aAddr + 16 * 128);
                    uint32_t aAddrL = aAddr + 4 * BLK;
                    LDSM_X4(a0l[0], a0l[1], a0l[2], a0l[3], aAddrL);
                    LDSM_X4(a1l[0], a1l[1], a1l[2], a1l[3], aAddrL + 16 * 128);
                    #pragma unroll
                    for (int nt = 0; nt < 8; nt++) {
                        uint32_t bf0 = bb[nt >> 1][(nt & 1) * 2];
                        uint32_t bf1 = bb[nt >> 1][(nt & 1) * 2 + 1];
                        MMA_BF16(acc[0][nt], a0h[0], a0h[1], a0h[2], a0h[3], bf0, bf1);
                        MMA_BF16(acc[1][nt], a1h[0], a1h[1], a1h[2], a1h[3], bf0, bf1);
                    }
                    #pragma unroll
                    for (int nt = 0; nt < 8; nt++) {
                        uint32_t bf0 = bb[nt >> 1][(nt & 1) * 2];
                        uint32_t bf1 = bb[nt >> 1][(nt & 1) * 2 + 1];
                        MMA_BF16(acc[0][nt], a0l[0], a0l[1], a0l[2], a0l[3], bf0, bf1);
                        MMA_BF16(acc[1][nt], a1l[0], a1l[1], a1l[2], a1l[3], bf0, bf1);
                    }
                }
                if (lane == 0) MBAR_ARRIVE(sb + SM_KEMPTY + 8 * ks);
                if (++ks == KST) { ks = 0; kph ^= 1; }
            }

            // fold tile into running per-lane top-4 (ascending n order)
            #pragma unroll
            for (int mt = 0; mt < 2; mt++)
                #pragma unroll
                for (int half = 0; half < 2; half++) {
                    const int s = mt * 2 + half;
                    #pragma unroll
                    for (int nt = 0; nt < 8; nt++)
                        #pragma unroll
                        for (int jj = 0; jj < 2; jj++) {
                            float v = acc[mt][nt][half * 2 + jj];
                            int n = c * 128 + wn * 64 + nt * 8 + cq * 2 + jj;
                            ins4(v, n, tv[s], ti[s]);
                        }
                }
        }

        // quad reduction (lanes cq=0..3 share each row)
        #pragma unroll
        for (int o = 1; o <= 2; o <<= 1)
            #pragma unroll
            for (int s = 0; s < 4; s++) {
                float wv[4]; int wk[4];
                #pragma unroll
                for (int r = 0; r < 4; r++) {
                    wv[r] = __shfl_xor_sync(0xffffffffu, tv[s][r], o);
                    wk[r] = __shfl_xor_sync(0xffffffffu, ti[s][r], o);
                }
                #pragma unroll
                for (int r = 0; r < 4; r++) ins4(wv[r], wk[r], tv[s], ti[s]);
            }
        if (cq == 0) {
            #pragma unroll
            for (int s = 0; s < 4; s++) {
                int row = wm * 32 + (s >> 1) * 16 + (s & 1) * 8 + g;
                sv4v[row * 2 + wn] = make_uint4(__float_as_uint(tv[s][0]),
                                                __float_as_uint(tv[s][1]),
                                                __float_as_uint(tv[s][2]),
                                                __float_as_uint(tv[s][3]));
                sv4i[row * 2 + wn] = make_uint4((uint32_t)ti[s][0], (uint32_t)ti[s][1],
                                                (uint32_t)ti[s][2], (uint32_t)ti[s][3]);
            }
        }
    }
    __syncthreads();
    if (tid < MT) {
        uint4 av = sv4v[tid * 2],     ai = sv4i[tid * 2];
        uint4 bv = sv4v[tid * 2 + 1], bi = sv4i[tid * 2 + 1];
        float mv[4] = {__uint_as_float(av.x), __uint_as_float(av.y),
                       __uint_as_float(av.z), __uint_as_float(av.w)};
        int   mi[4] = {(int)ai.x, (int)ai.y, (int)ai.z, (int)ai.w};
        ins4(__uint_as_float(bv.x), (int)bi.x, mv, mi);
        ins4(__uint_as_float(bv.y), (int)bi.y, mv, mi);
        ins4(__uint_as_float(bv.z), (int)bi.z, mv, mi);
        ins4(__uint_as_float(bv.w), (int)bi.w, mv, mi);
        g_top4[blockIdx.x * MT + tid] = make_int4(mi[0], mi[1], mi[2], mi[3]);
    }
}

// ---------------------------------------------------------------------------
// Kernel 4: exact fp32 rescore of top-4 + projection/loss epilogue.
// One warp per row. Output: [x_q (B*D) | loss (1) | indices (B) | scalar (B)]
// ---------------------------------------------------------------------------
__global__ void epilogue_kernel(const float* __restrict__ X,
                                const float* __restrict__ E,
                                float* __restrict__ out) {
    const int gw   = (blockIdx.x * blockDim.x + threadIdx.x) >> 5;
    const int lane = threadIdx.x & 31;
    __shared__ float wsum[8];
    float contrib = 0.f;

    if (gw < B_) {
        const int b = gw;
        const int4 t4 = g_top4[b];
        const int cidx[4] = {t4.x, t4.y, t4.z, t4.w};
        const float4* xr = (const float4*)(X + (size_t)b * D_);
        float4 xv[2];
        float xsq = 0.f;
        #pragma unroll
        for (int r = 0; r < 2; r++) {
            xv[r] = xr[lane + r * 32];
            xsq += xv[r].x*xv[r].x + xv[r].y*xv[r].y + xv[r].z*xv[r].z + xv[r].w*xv[r].w;
        }
        float4 ev[4][2];
        float dots[4], nsqs[4];
        #pragma unroll
        for (int i = 0; i < 4; i++) {
            const float4* cr = (const float4*)(E + (size_t)cidx[i] * D_);
            float d = 0.f, nn = 0.f;
            #pragma unroll
            for (int r = 0; r < 2; r++) {
                ev[i][r] = cr[lane + r * 32];
                d  += xv[r].x*ev[i][r].x + xv[r].y*ev[i][r].y
                    + xv[r].z*ev[i][r].z + xv[r].w*ev[i][r].w;
                nn += ev[i][r].x*ev[i][r].x + ev[i][r].y*ev[i][r].y
                    + ev[i][r].z*ev[i][r].z + ev[i][r].w*ev[i][r].w;
            }
            dots[i] = d; nsqs[i] = nn;
        }
        #pragma unroll
        for (int o = 16; o; o >>= 1) {
            xsq += __shfl_xor_sync(0xffffffffu, xsq, o);
            #pragma unroll
            for (int i = 0; i < 4; i++) {
                dots[i] += __shfl_xor_sync(0xffffffffu, dots[i], o);
                nsqs[i] += __shfl_xor_sync(0xffffffffu, nsqs[i], o);
            }
        }
        // exact selection: argmax of x.e / max(||e||,eps), lowest index on tie
        int   bidx = cidx[0];
        float bs   = dots[0] / fmaxf(sqrtf(nsqs[0]), 1e-12f);
        float bdot = dots[0], bnsq = nsqs[0];
        int   bsel = 0;
        #pragma unroll
        for (int i = 1; i < 4; i++) {
            float si = dots[i] / fmaxf(sqrtf(nsqs[i]), 1e-12f);
            if (si > bs || (si == bs && cidx[i] < bidx)) {
                bs = si; bidx = cidx[i]; bdot = dots[i]; bnsq = nsqs[i]; bsel = i;
            }
        }
        const float scalar = bdot / (bnsq + 1e-8f);

        float4* orow = (float4*)(out + (size_t)b * D_);
        #pragma unroll
        for (int r = 0; r < 2; r++) {
            float4 cv = ev[0][r];
            if (bsel == 1) cv = ev[1][r];
            else if (bsel == 2) cv = ev[2][r];
            else if (bsel == 3) cv = ev[3][r];
            float4 o;
            o.x = xv[r].x + (scalar * cv.x - xv[r].x);
            o.y = xv[r].y + (scalar * cv.y - xv[r].y);
            o.z = xv[r].z + (scalar * cv.z - xv[r].z);
            o.w = xv[r].w + (scalar * cv.w - xv[r].w);
            orow[lane + r * 32] = o;
        }
        if (lane == 0) {
            out[(size_t)B_ * D_ + 1 + b]      = (float)bidx;
            out[(size_t)B_ * D_ + 1 + B_ + b] = scalar;
            const float nproj = fabsf(scalar) * sqrtf(bnsq);
            const float nx = sqrtf(xsq);
            const float commit = (scalar * bdot) /
                (fmaxf(nproj, 1e-8f) * fmaxf(nx, 1e-8f));
            contrib = 1.f - commit;
        }
    }
    const int w = threadIdx.x >> 5;
    if (lane == 0) wsum[w] = contrib;
    __syncthreads();
    if (threadIdx.x == 0) {
        float s = 0.f;
        #pragma unroll
        for (int i = 0; i < 8; i++) s += wsum[i];
        g_partial[blockIdx.x] = s;
    }
}

// ---------------------------------------------------------------------------
// Kernel 5: deterministic final loss reduction.
// ---------------------------------------------------------------------------
__global__ void loss_kernel(float* __restrict__ out) {
    __shared__ double red[256];
    const int t = threadIdx.x;
    double s = 0.0;
    for (int i = t; i < EPI_BLOCKS; i += 256) s += (double)g_partial[i];
    red[t] = s;
    __syncthreads();
    for (int o = 128; o; o >>= 1) {
        if (t < o) red[t] += red[t + o];
        __syncthreads();
    }
    if (t == 0) out[(size_t)B_ * D_] = (float)(0.25 * red[0] / (double)B_);
}

// ---------------------------------------------------------------------------
extern "C" void kernel_launch(void* const* d_in, const int* in_sizes, int n_in,
                              void* d_out, int out_size) {
    const float* X = (const float*)d_in[0];   // (32768, 256) fp32
    const float* E = (const float*)d_in[1];   // (8192, 256) fp32
    float* out = (float*)d_out;

    cudaFuncSetAttribute(mma_argmax_kernel,
                         cudaFuncAttributeMaxDynamicSharedMemorySize, SMEM_TOTAL);

    split_x_kernel<<<B_ * 32 / 256, 256>>>(X);
    split_cb_kernel<<<N_, 256>>>(E);
    mma_argmax_kernel<<<MTILES, 288, SMEM_TOTAL>>>();
    epilogue_kernel<<<EPI_BLOCKS, 256>>>(X, E, out);
    loss_kernel<<<1, 256>>>(out);
}

// round 8
// speedup vs baseline: 1.2848x; 1.2848x over previous
#include <cuda_runtime.h>
#include <cuda_bf16.h>
#include <math.h>
#include <stdint.h>

// ---------------------------------------------------------------------------
// Problem constants
// ---------------------------------------------------------------------------
#define B_ 32768
#define D_ 256
#define N_ 8192

#define MT 128              // M rows per CTA
#define NTILE 128           // N cols per B stream block
#define NTILES (N_ / NTILE) // 64
#define MTILES (B_ / MT)    // 256
#define KST 4               // B smem ring stages

#define BLK 16384           // one k64 block: 128 rows x 64 bf16 (SW128-swizzled)

// dynamic smem layout
#define SM_AFULL  8
#define SM_KFULL  16        // 4 x 8B  (16..47)
#define SM_KEMPTY 48        // 4 x 8B  (48..79)
#define SM_SV4V   128       // uint4[128][2] values  (4KB)
#define SM_SV4I   4224      // uint4[128][2] indices (4KB)
#define SM_A      8448      // 8 x 16KB = 128KB (hi0-3, lo0-3)
#define SM_B      (SM_A + 8 * BLK)       // 139520
#define SMEM_TOTAL (SM_B + KST * BLK)    // 205056

#define EPI_BLOCKS (B_ / 8)

// ---------------------------------------------------------------------------
// Global scratch
// ---------------------------------------------------------------------------
__device__ __align__(16) uint8_t g_Asw[(size_t)MTILES * 8 * BLK];  // 32 MB
__device__ __align__(16) uint8_t g_Bsw[(size_t)NTILES * 4 * BLK];  // 4 MB (hi only)
__device__ int4  g_top4[B_];
__device__ float g_partial[EPI_BLOCKS];

// ---------------------------------------------------------------------------
// PTX helpers (family-wide features only — NO tcgen05 at compute_103)
// ---------------------------------------------------------------------------
__device__ __forceinline__ uint32_t smem_u32(const void* p) {
    uint32_t a;
    asm("{ .reg .u64 t; cvta.to.shared.u64 t, %1; cvt.u32.u64 %0, t; }"
        : "=r"(a) : "l"(p));
    return a;
}
__device__ __forceinline__ uint32_t elect_one() {
    uint32_t pred;
    asm volatile("{\n\t.reg .pred p;\n\telect.sync _|p, 0xFFFFFFFF;\n\t"
                 "selp.b32 %0, 1, 0, p;\n\t}" : "=r"(pred));
    return pred;
}
#define MBAR_INIT(addr, cnt) \
    asm volatile("mbarrier.init.shared.b64 [%0], %1;" :: "r"(addr), "r"(cnt) : "memory")
#define MBAR_EXPECT_TX(addr, bytes) \
    asm volatile("mbarrier.arrive.expect_tx.shared.b64 _, [%0], %1;" \
                 :: "r"(addr), "r"(bytes) : "memory")
#define MBAR_ARRIVE(addr) \
    asm volatile("mbarrier.arrive.shared.b64 _, [%0];" :: "r"(addr) : "memory")
#define MBAR_WAIT(addr, ph) do {                                              \
    uint32_t _m = (addr), _p = (ph), _d;                                      \
    asm volatile("{\n\t.reg .pred p;\n\t"                                     \
        "mbarrier.try_wait.parity.acquire.cta.shared::cta.b64 p, [%1], %2;\n\t" \
        "selp.b32 %0, 1, 0, p;\n\t}" : "=r"(_d) : "r"(_m), "r"(_p) : "memory");\
    if (!_d) {                                                                \
        asm volatile("{\n\t.reg .pred P1;\n\t"                                \
            "WL_%=:\n\t"                                                      \
            "mbarrier.try_wait.parity.acquire.cta.shared::cta.b64 P1, [%0], %1, 0x989680;\n\t" \
            "@P1 bra.uni WD_%=;\n\t"                                          \
            "bra.uni WL_%=;\n\t"                                              \
            "WD_%=:\n\t}" :: "r"(_m), "r"(_p) : "memory");                    \
    } } while (0)
#define BULK_G2S(dst, src, bytes, mbar) \
    asm volatile("cp.async.bulk.shared::cta.global.mbarrier::complete_tx::bytes " \
                 "[%0], [%1], %2, [%3];" \
                 :: "r"(dst), "l"(src), "r"(bytes), "r"(mbar) : "memory")
#define LDSM_X4(r0, r1, r2, r3, a) \
    asm volatile("ldmatrix.sync.aligned.m8n8.x4.shared.b16 {%0,%1,%2,%3}, [%4];" \
        : "=r"(r0), "=r"(r1), "=r"(r2), "=r"(r3) : "r"(a))
#define MMA_BF16(d, a0, a1, a2, a3, b0, b1) \
    asm volatile("mma.sync.aligned.m16n8k16.row.col.f32.bf16.bf16.f32 " \
        "{%0,%1,%2,%3}, {%4,%5,%6,%7}, {%8,%9}, {%0,%1,%2,%3};" \
        : "+f"((d)[0]), "+f"((d)[1]), "+f"((d)[2]), "+f"((d)[3]) \
        : "r"(a0), "r"(a1), "r"(a2), "r"(a3), "r"(b0), "r"(b1))

union Pack8 { __nv_bfloat16 h[8]; uint4 v; };

__device__ __forceinline__ bool better(float v, int i, float w, int k) {
    return v > w || (v == w && i < k);
}
// Insert (v,n) into desc-sorted top-4 list (general, with index tie-break).
__device__ __forceinline__ void ins4(float v, int n, float tv[4], int ti[4]) {
    if (!better(v, n, tv[3], ti[3])) return;
    if (better(v, n, tv[0], ti[0])) {
        tv[3]=tv[2]; ti[3]=ti[2]; tv[2]=tv[1]; ti[2]=ti[1];
        tv[1]=tv[0]; ti[1]=ti[0]; tv[0]=v; ti[0]=n;
    } else if (better(v, n, tv[1], ti[1])) {
        tv[3]=tv[2]; ti[3]=ti[2]; tv[2]=tv[1]; ti[2]=ti[1]; tv[1]=v; ti[1]=n;
    } else if (better(v, n, tv[2], ti[2])) {
        tv[3]=tv[2]; ti[3]=ti[2]; tv[2]=v; ti[2]=n;
    } else { tv[3]=v; ti[3]=n; }
}
// Streaming insert: per-lane n is strictly ascending, so ties always lose —
// strict > comparisons only, guarded by the cheap common-path check.
__device__ __forceinline__ void ins4_stream(float v, int n, float tv[4], int ti[4]) {
    if (v > tv[3]) {
        if (v > tv[0]) {
            tv[3]=tv[2]; ti[3]=ti[2]; tv[2]=tv[1]; ti[2]=ti[1];
            tv[1]=tv[0]; ti[1]=ti[0]; tv[0]=v; ti[0]=n;
        } else if (v > tv[1]) {
            tv[3]=tv[2]; ti[3]=ti[2]; tv[2]=tv[1]; ti[2]=ti[1]; tv[1]=v; ti[1]=n;
        } else if (v > tv[2]) {
            tv[3]=tv[2]; ti[3]=ti[2]; tv[2]=v; ti[2]=n;
        } else { tv[3]=v; ti[3]=n; }
    }
}

// ---------------------------------------------------------------------------
// Kernel 1: split X into bf16 hi/lo, pre-swizzled SW128 16KB blocks.
// ---------------------------------------------------------------------------
__global__ void split_x_kernel(const float* __restrict__ X) {
    int g = blockIdx.x * 256 + threadIdx.x;
    int b  = g >> 5;
    int cg = g & 31;
    const float4* xp = (const float4*)(X + (size_t)b * D_ + cg * 8);
    float4 x0 = xp[0], x1 = xp[1];
    float xs[8] = {x0.x, x0.y, x0.z, x0.w, x1.x, x1.y, x1.z, x1.w};
    Pack8 hi, lo;
    #pragma unroll
    for (int i = 0; i < 8; i++) {
        __nv_bfloat16 h = __float2bfloat16(xs[i]);
        hi.h[i] = h;
        lo.h[i] = __float2bfloat16(xs[i] - __bfloat162float(h));
    }
    int mtile = b >> 7, m = b & 127, kc = cg >> 3;
    uint32_t off = m * 128 + (cg & 7) * 16;
    uint32_t sw = off ^ ((off >> 3) & 0x70);
    *(uint4*)(g_Asw + ((size_t)(mtile * 8 + kc)) * BLK + sw) = hi.v;
    *(uint4*)(g_Asw + ((size_t)(mtile * 8 + 4 + kc)) * BLK + sw) = lo.v;
}

// ---------------------------------------------------------------------------
// Kernel 2: normalize codebook rows, bf16 hi only, pre-swizzled blocks.
// ---------------------------------------------------------------------------
__global__ void split_cb_kernel(const float* __restrict__ E) {
    int n = blockIdx.x;
    int t = threadIdx.x;
    float v = E[(size_t)n * D_ + t];
    float s = v * v;
    #pragma unroll
    for (int o = 16; o; o >>= 1) s += __shfl_xor_sync(0xffffffffu, s, o);
    __shared__ float red[8];
    __shared__ float sv[256];
    if ((t & 31) == 0) red[t >> 5] = s;
    __syncthreads();
    if (t == 0) {
        float tot = 0.f;
        #pragma unroll
        for (int i = 0; i < 8; i++) tot += red[i];
        red[0] = fmaxf(sqrtf(tot), 1e-12f);
    }
    __syncthreads();
    sv[t] = v / red[0];
    __syncthreads();
    if (t < 32) {
        int cg = t;
        Pack8 u;
        #pragma unroll
        for (int i = 0; i < 8; i++) u.h[i] = __float2bfloat16(sv[cg * 8 + i]);
        int nc = n >> 7, r = n & 127, kc = cg >> 3;
        uint32_t off = r * 128 + (cg & 7) * 16;
        uint32_t sw = off ^ ((off >> 3) & 0x70);
        *(uint4*)(g_Bsw + ((size_t)(nc * 4 + kc)) * BLK + sw) = u.v;
    }
}

// ---------------------------------------------------------------------------
// One k64 step (EXACT R6 structure): 4x k16 {2 A ldmatrix, 4 B ldmatrix, 16 mma}.
// ---------------------------------------------------------------------------
__device__ __forceinline__ void kstep(uint32_t aBase, uint32_t bBase,
                                      float acc[2][8][4],
                                      int a_kbh, int b_rowoff, int b_kbh, int sx) {
    #pragma unroll
    for (int q = 0; q < 4; q++) {
        uint32_t a0[4], a1[4];
        uint32_t aAddr = aBase + ((q * 32 + a_kbh) ^ sx);
        LDSM_X4(a0[0], a0[1], a0[2], a0[3], aAddr);
        LDSM_X4(a1[0], a1[1], a1[2], a1[3], aAddr + 16 * 128);
        uint32_t bb[4][4];
        #pragma unroll
        for (int p = 0; p < 4; p++) {
            uint32_t bAddr = bBase + (p * 16 + b_rowoff) * 128 + ((q * 32 + b_kbh) ^ sx);
            LDSM_X4(bb[p][0], bb[p][1], bb[p][2], bb[p][3], bAddr);
        }
        #pragma unroll
        for (int nt = 0; nt < 8; nt++) {
            uint32_t bf0 = bb[nt >> 1][(nt & 1) * 2];
            uint32_t bf1 = bb[nt >> 1][(nt & 1) * 2 + 1];
            MMA_BF16(acc[0][nt], a0[0], a0[1], a0[2], a0[3], bf0, bf1);
            MMA_BF16(acc[1][nt], a1[0], a1[1], a1[2], a1[3], bf0, bf1);
        }
    }
}

// ---------------------------------------------------------------------------
// Kernel 3: HMMA GEMM (2 terms: hi_x.hi_e + lo_x.hi_e) + per-row top-4.
// 288 threads: warps 0-7 compute (4x2 warp grid, 32x64 tiles); warp 8 produces.
// Per B stage: kstep(A-hi) then kstep(A-lo), R6-style separate calls.
// ---------------------------------------------------------------------------
__global__ __launch_bounds__(288, 1) void mma_argmax_kernel() {
    extern __shared__ char smem[];
    const uint32_t sb = smem_u32(smem);
    uint4* sv4v = (uint4*)(smem + SM_SV4V);
    uint4* sv4i = (uint4*)(smem + SM_SV4I);
    const int tid = threadIdx.x, wid = tid >> 5, lane = tid & 31;

    if (tid == 0) {
        MBAR_INIT(sb + SM_AFULL, 1);
        #pragma unroll
        for (int s = 0; s < KST; s++) {
            MBAR_INIT(sb + SM_KFULL + 8 * s, 1);
            MBAR_INIT(sb + SM_KEMPTY + 8 * s, 8);
        }
        asm volatile("fence.proxy.async.shared::cta;" ::: "memory");
    }
    __syncthreads();

    if (wid == 8) {
        // ---- producer: A once (8 x 16KB), then B hi ring (4 blocks / tile) ----
        if (elect_one()) {
            MBAR_EXPECT_TX(sb + SM_AFULL, 8 * BLK);
            #pragma unroll
            for (int blk = 0; blk < 8; blk++)
                BULK_G2S(sb + SM_A + blk * BLK,
                         g_Asw + ((size_t)blockIdx.x * 8 + blk) * BLK,
                         BLK, sb + SM_AFULL);
            int ks = 0, kph = 1;
            for (int c = 0; c < NTILES; c++) {
                for (int t = 0; t < 4; t++) {
                    MBAR_WAIT(sb + SM_KEMPTY + 8 * ks, kph);
                    MBAR_EXPECT_TX(sb + SM_KFULL + 8 * ks, BLK);
                    BULK_G2S(sb + SM_B + ks * BLK,
                             g_Bsw + ((size_t)c * 4 + t) * BLK,
                             BLK, sb + SM_KFULL + 8 * ks);
                    if (++ks == KST) { ks = 0; kph ^= 1; }
                }
            }
        }
    } else {
        // ---- compute warps ----
        const int wm = wid >> 1, wn = wid & 1;
        const int sx = (lane & 7) * 16;
        const int a_row0 = lane & 15;
        const int a_kbh = (lane >> 4) * 16;
        const int b_rowoff = ((lane >> 4) & 1) * 8 + (lane & 7);
        const int b_kbh = ((lane >> 3) & 1) * 16;
        const uint32_t aWarp = sb + SM_A + wm * 4096 + a_row0 * 128;
        const int g = lane >> 2, cq = lane & 3;

        float tv[4][4];
        int   ti[4][4];
        #pragma unroll
        for (int s = 0; s < 4; s++)
            #pragma unroll
            for (int r = 0; r < 4; r++) { tv[s][r] = -3.4e38f; ti[s][r] = 0x7fffffff; }

        MBAR_WAIT(sb + SM_AFULL, 0);

        int ks = 0, kph = 0;
        for (int c = 0; c < NTILES; c++) {
            float acc[2][8][4];
            #pragma unroll
            for (int mt = 0; mt < 2; mt++)
                #pragma unroll
                for (int nt = 0; nt < 8; nt++)
                    #pragma unroll
                    for (int r = 0; r < 4; r++) acc[mt][nt][r] = 0.f;

            #pragma unroll 1
            for (int j = 0; j < 4; j++) {   // B hi_j: A hi_j pass, then A lo_j pass
                MBAR_WAIT(sb + SM_KFULL + 8 * ks, kph);
                const uint32_t bBase = sb + SM_B + ks * BLK + wn * 8192;
                kstep(aWarp + j * BLK, bBase, acc, a_kbh, b_rowoff, b_kbh, sx);
                kstep(aWarp + (4 + j) * BLK, bBase, acc, a_kbh, b_rowoff, b_kbh, sx);
                if (lane == 0) MBAR_ARRIVE(sb + SM_KEMPTY + 8 * ks);
                if (++ks == KST) { ks = 0; kph ^= 1; }
            }

            // fold tile into running per-lane top-4 (ascending n per lane)
            #pragma unroll
            for (int mt = 0; mt < 2; mt++)
                #pragma unroll
                for (int half = 0; half < 2; half++) {
                    const int s = mt * 2 + half;
                    #pragma unroll
                    for (int nt = 0; nt < 8; nt++)
                        #pragma unroll
                        for (int jj = 0; jj < 2; jj++) {
                            float v = acc[mt][nt][half * 2 + jj];
                            int n = c * 128 + wn * 64 + nt * 8 + cq * 2 + jj;
                            ins4_stream(v, n, tv[s], ti[s]);
                        }
                }
        }

        // quad reduction (lanes cq=0..3 share each row)
        #pragma unroll
        for (int o = 1; o <= 2; o <<= 1)
            #pragma unroll
            for (int s = 0; s < 4; s++) {
                float wv[4]; int wk[4];
                #pragma unroll
                for (int r = 0; r < 4; r++) {
                    wv[r] = __shfl_xor_sync(0xffffffffu, tv[s][r], o);
                    wk[r] = __shfl_xor_sync(0xffffffffu, ti[s][r], o);
                }
                #pragma unroll
                for (int r = 0; r < 4; r++) ins4(wv[r], wk[r], tv[s], ti[s]);
            }
        if (cq == 0) {
            #pragma unroll
            for (int s = 0; s < 4; s++) {
                int row = wm * 32 + (s >> 1) * 16 + (s & 1) * 8 + g;
                sv4v[row * 2 + wn] = make_uint4(__float_as_uint(tv[s][0]),
                                                __float_as_uint(tv[s][1]),
                                                __float_as_uint(tv[s][2]),
                                                __float_as_uint(tv[s][3]));
                sv4i[row * 2 + wn] = make_uint4((uint32_t)ti[s][0], (uint32_t)ti[s][1],
                                                (uint32_t)ti[s][2], (uint32_t)ti[s][3]);
            }
        }
    }
    __syncthreads();
    if (tid < MT) {
        uint4 av = sv4v[tid * 2],     ai = sv4i[tid * 2];
        uint4 bv = sv4v[tid * 2 + 1], bi = sv4i[tid * 2 + 1];
        float mv[4] = {__uint_as_float(av.x), __uint_as_float(av.y),
                       __uint_as_float(av.z), __uint_as_float(av.w)};
        int   mi[4] = {(int)ai.x, (int)ai.y, (int)ai.z, (int)ai.w};
        ins4(__uint_as_float(bv.x), (int)bi.x, mv, mi);
        ins4(__uint_as_float(bv.y), (int)bi.y, mv, mi);
        ins4(__uint_as_float(bv.z), (int)bi.z, mv, mi);
        ins4(__uint_as_float(bv.w), (int)bi.w, mv, mi);
        g_top4[blockIdx.x * MT + tid] = make_int4(mi[0], mi[1], mi[2], mi[3]);
    }
}

// ---------------------------------------------------------------------------
// Kernel 4: exact fp32 rescore of top-4 + projection/loss epilogue.
// One warp per row. Output: [x_q (B*D) | loss (1) | indices (B) | scalar (B)]
// ---------------------------------------------------------------------------
__global__ void epilogue_kernel(const float* __restrict__ X,
                                const float* __restrict__ E,
                                float* __restrict__ out) {
    const int gw   = (blockIdx.x * blockDim.x + threadIdx.x) >> 5;
    const int lane = threadIdx.x & 31;
    __shared__ float wsum[8];
    float contrib = 0.f;

    if (gw < B_) {
        const int b = gw;
        const int4 t4 = g_top4[b];
        const int cidx[4] = {t4.x, t4.y, t4.z, t4.w};
        const float4* xr = (const float4*)(X + (size_t)b * D_);
        float4 xv[2];
        float xsq = 0.f;
        #pragma unroll
        for (int r = 0; r < 2; r++) {
            xv[r] = xr[lane + r * 32];
            xsq += xv[r].x*xv[r].x + xv[r].y*xv[r].y + xv[r].z*xv[r].z + xv[r].w*xv[r].w;
        }
        float4 ev[4][2];
        float dots[4], nsqs[4];
        #pragma unroll
        for (int i = 0; i < 4; i++) {
            const float4* cr = (const float4*)(E + (size_t)cidx[i] * D_);
            float d = 0.f, nn = 0.f;
            #pragma unroll
            for (int r = 0; r < 2; r++) {
                ev[i][r] = cr[lane + r * 32];
                d  += xv[r].x*ev[i][r].x + xv[r].y*ev[i][r].y
                    + xv[r].z*ev[i][r].z + xv[r].w*ev[i][r].w;
                nn += ev[i][r].x*ev[i][r].x + ev[i][r].y*ev[i][r].y
                    + ev[i][r].z*ev[i][r].z + ev[i][r].w*ev[i][r].w;
            }
            dots[i] = d; nsqs[i] = nn;
        }
        #pragma unroll
        for (int o = 16; o; o >>= 1) {
            xsq += __shfl_xor_sync(0xffffffffu, xsq, o);
            #pragma unroll
            for (int i = 0; i < 4; i++) {
                dots[i] += __shfl_xor_sync(0xffffffffu, dots[i], o);
                nsqs[i] += __shfl_xor_sync(0xffffffffu, nsqs[i], o);
            }
        }
        // exact selection: argmax of x.e / max(||e||,eps), lowest index on tie
        int   bidx = cidx[0];
        float bs   = dots[0] / fmaxf(sqrtf(nsqs[0]), 1e-12f);
        float bdot = dots[0], bnsq = nsqs[0];
        int   bsel = 0;
        #pragma unroll
        for (int i = 1; i < 4; i++) {
            float si = dots[i] / fmaxf(sqrtf(nsqs[i]), 1e-12f);
            if (si > bs || (si == bs && cidx[i] < bidx)) {
                bs = si; bidx = cidx[i]; bdot = dots[i]; bnsq = nsqs[i]; bsel = i;
            }
        }
        const float scalar = bdot / (bnsq + 1e-8f);

        float4* orow = (float4*)(out + (size_t)b * D_);
        #pragma unroll
        for (int r = 0; r < 2; r++) {
            float4 cv = ev[0][r];
            if (bsel == 1) cv = ev[1][r];
            else if (bsel == 2) cv = ev[2][r];
            else if (bsel == 3) cv = ev[3][r];
            float4 o;
            o.x = xv[r].x + (scalar * cv.x - xv[r].x);
            o.y = xv[r].y + (scalar * cv.y - xv[r].y);
            o.z = xv[r].z + (scalar * cv.z - xv[r].z);
            o.w = xv[r].w + (scalar * cv.w - xv[r].w);
            orow[lane + r * 32] = o;
        }
        if (lane == 0) {
            out[(size_t)B_ * D_ + 1 + b]      = (float)bidx;
            out[(size_t)B_ * D_ + 1 + B_ + b] = scalar;
            const float nproj = fabsf(scalar) * sqrtf(bnsq);
            const float nx = sqrtf(xsq);
            const float commit = (scalar * bdot) /
                (fmaxf(nproj, 1e-8f) * fmaxf(nx, 1e-8f));
            contrib = 1.f - commit;
        }
    }
    const int w = threadIdx.x >> 5;
    if (lane == 0) wsum[w] = contrib;
    __syncthreads();
    if (threadIdx.x == 0) {
        float s = 0.f;
        #pragma unroll
        for (int i = 0; i < 8; i++) s += wsum[i];
        g_partial[blockIdx.x] = s;
    }
}

// ---------------------------------------------------------------------------
// Kernel 5: deterministic final loss reduction.
// ---------------------------------------------------------------------------
__global__ void loss_kernel(float* __restrict__ out) {
    __shared__ double red[256];
    const int t = threadIdx.x;
    double s = 0.0;
    for (int i = t; i < EPI_BLOCKS; i += 256) s += (double)g_partial[i];
    red[t] = s;
    __syncthreads();
    for (int o = 128; o; o >>= 1) {
        if (t < o) red[t] += red[t + o];
        __syncthreads();
    }
    if (t == 0) out[(size_t)B_ * D_] = (float)(0.25 * red[0] / (double)B_);
}

// ---------------------------------------------------------------------------
extern "C" void kernel_launch(void* const* d_in, const int* in_sizes, int n_in,
                              void* d_out, int out_size) {
    const float* X = (const float*)d_in[0];   // (32768, 256) fp32
    const float* E = (const float*)d_in[1];   // (8192, 256) fp32
    float* out = (float*)d_out;

    cudaFuncSetAttribute(mma_argmax_kernel,
                         cudaFuncAttributeMaxDynamicSharedMemorySize, SMEM_TOTAL);

    split_x_kernel<<<B_ * 32 / 256, 256>>>(X);
    split_cb_kernel<<<N_, 256>>>(E);
    mma_argmax_kernel<<<MTILES, 288, SMEM_TOTAL>>>();
    epilogue_kernel<<<EPI_BLOCKS, 256>>>(X, E, out);
    loss_kernel<<<1, 256>>>(out);
}

// round 9
// speedup vs baseline: 2.4887x; 1.9371x over previous
#include <cuda_runtime.h>
#include <cuda_bf16.h>
#include <math.h>
#include <stdint.h>

// ---------------------------------------------------------------------------
// Problem constants
// ---------------------------------------------------------------------------
#define B_ 32768
#define D_ 256
#define N_ 8192

#define MT 128              // M rows per CTA
#define NTILE 128           // N cols per B stream block
#define NTILES (N_ / NTILE) // 64
#define MTILES (B_ / MT)    // 256
#define KST 4               // B smem ring stages

#define BLK 16384           // one k64 block: 128 rows x 64 bf16 (SW128-swizzled)

// dynamic smem layout
#define SM_AFULL  8
#define SM_KFULL  16        // 4 x 8B  (16..47)
#define SM_KEMPTY 48        // 4 x 8B  (48..79)
#define SM_SV2    128       // uint4[128][2] = 4KB
#define SM_A      8192      // 8 x 16KB = 128KB  (hi0-3, lo0-3)
#define SM_B      (SM_A + 8 * BLK)       // 139264
#define SMEM_TOTAL (SM_B + KST * BLK)    // 204800

#define EPI_BLOCKS (B_ / 8)

// ---------------------------------------------------------------------------
// Global scratch
// ---------------------------------------------------------------------------
__device__ __align__(16) uint8_t g_Asw[(size_t)MTILES * 8 * BLK];  // 32 MB
__device__ __align__(16) uint8_t g_Bsw[(size_t)NTILES * 4 * BLK];  // 4 MB (hi only)
__device__ int4  g_top4[B_];
__device__ float g_partial[EPI_BLOCKS];

// ---------------------------------------------------------------------------
// PTX helpers (family-wide features only — NO tcgen05 at compute_103)
// ---------------------------------------------------------------------------
__device__ __forceinline__ uint32_t smem_u32(const void* p) {
    uint32_t a;
    asm("{ .reg .u64 t; cvta.to.shared.u64 t, %1; cvt.u32.u64 %0, t; }"
        : "=r"(a) : "l"(p));
    return a;
}
__device__ __forceinline__ uint32_t elect_one() {
    uint32_t pred;
    asm volatile("{\n\t.reg .pred p;\n\telect.sync _|p, 0xFFFFFFFF;\n\t"
                 "selp.b32 %0, 1, 0, p;\n\t}" : "=r"(pred));
    return pred;
}
#define MBAR_INIT(addr, cnt) \
    asm volatile("mbarrier.init.shared.b64 [%0], %1;" :: "r"(addr), "r"(cnt) : "memory")
#define MBAR_EXPECT_TX(addr, bytes) \
    asm volatile("mbarrier.arrive.expect_tx.shared.b64 _, [%0], %1;" \
                 :: "r"(addr), "r"(bytes) : "memory")
#define MBAR_ARRIVE(addr) \
    asm volatile("mbarrier.arrive.shared.b64 _, [%0];" :: "r"(addr) : "memory")
#define MBAR_WAIT(addr, ph) do {                                              \
    uint32_t _m = (addr), _p = (ph), _d;                                      \
    asm volatile("{\n\t.reg .pred p;\n\t"                                     \
        "mbarrier.try_wait.parity.acquire.cta.shared::cta.b64 p, [%1], %2;\n\t" \
        "selp.b32 %0, 1, 0, p;\n\t}" : "=r"(_d) : "r"(_m), "r"(_p) : "memory");\
    if (!_d) {                                                                \
        asm volatile("{\n\t.reg .pred P1;\n\t"                                \
            "WL_%=:\n\t"                                                      \
            "mbarrier.try_wait.parity.acquire.cta.shared::cta.b64 P1, [%0], %1, 0x989680;\n\t" \
            "@P1 bra.uni WD_%=;\n\t"                                          \
            "bra.uni WL_%=;\n\t"                                              \
            "WD_%=:\n\t}" :: "r"(_m), "r"(_p) : "memory");                    \
    } } while (0)
#define BULK_G2S(dst, src, bytes, mbar) \
    asm volatile("cp.async.bulk.shared::cta.global.mbarrier::complete_tx::bytes " \
                 "[%0], [%1], %2, [%3];" \
                 :: "r"(dst), "l"(src), "r"(bytes), "r"(mbar) : "memory")
#define LDSM_X4(r0, r1, r2, r3, a) \
    asm volatile("ldmatrix.sync.aligned.m8n8.x4.shared.b16 {%0,%1,%2,%3}, [%4];" \
        : "=r"(r0), "=r"(r1), "=r"(r2), "=r"(r3) : "r"(a))
#define MMA_BF16(d, a0, a1, a2, a3, b0, b1) \
    asm volatile("mma.sync.aligned.m16n8k16.row.col.f32.bf16.bf16.f32 " \
        "{%0,%1,%2,%3}, {%4,%5,%6,%7}, {%8,%9}, {%0,%1,%2,%3};" \
        : "+f"((d)[0]), "+f"((d)[1]), "+f"((d)[2]), "+f"((d)[3]) \
        : "r"(a0), "r"(a1), "r"(a2), "r"(a3), "r"(b0), "r"(b1))

union Pack8 { __nv_bfloat16 h[8]; uint4 v; };

__device__ __forceinline__ void merge_top2(float& v1, int& i1, float& v2, int& i2,
                                           float w1, int k1, float w2, int k2) {
    if (w1 > v1 || (w1 == v1 && k1 < i1)) {
        if (v1 > w2 || (v1 == w2 && i1 < k2)) { v2 = v1; i2 = i1; }
        else                                   { v2 = w2; i2 = k2; }
        v1 = w1; i1 = k1;
    } else if (w1 > v2 || (w1 == v2 && k1 < i2)) {
        v2 = w1; i2 = k1;
    }
}

// ---------------------------------------------------------------------------
// Kernel 1: split X into bf16 hi/lo, pre-swizzled SW128 16KB blocks.
// ---------------------------------------------------------------------------
__global__ void split_x_kernel(const float* __restrict__ X) {
    int g = blockIdx.x * 256 + threadIdx.x;
    int b  = g >> 5;
    int cg = g & 31;
    const float4* xp = (const float4*)(X + (size_t)b * D_ + cg * 8);
    float4 x0 = xp[0], x1 = xp[1];
    float xs[8] = {x0.x, x0.y, x0.z, x0.w, x1.x, x1.y, x1.z, x1.w};
    Pack8 hi, lo;
    #pragma unroll
    for (int i = 0; i < 8; i++) {
        __nv_bfloat16 h = __float2bfloat16(xs[i]);
        hi.h[i] = h;
        lo.h[i] = __float2bfloat16(xs[i] - __bfloat162float(h));
    }
    int mtile = b >> 7, m = b & 127, kc = cg >> 3;
    uint32_t off = m * 128 + (cg & 7) * 16;
    uint32_t sw = off ^ ((off >> 3) & 0x70);
    *(uint4*)(g_Asw + ((size_t)(mtile * 8 + kc)) * BLK + sw) = hi.v;
    *(uint4*)(g_Asw + ((size_t)(mtile * 8 + 4 + kc)) * BLK + sw) = lo.v;
}

// ---------------------------------------------------------------------------
// Kernel 2: normalize codebook rows, bf16 hi only, pre-swizzled blocks.
// ---------------------------------------------------------------------------
__global__ void split_cb_kernel(const float* __restrict__ E) {
    int n = blockIdx.x;
    int t = threadIdx.x;
    float v = E[(size_t)n * D_ + t];
    float s = v * v;
    #pragma unroll
    for (int o = 16; o; o >>= 1) s += __shfl_xor_sync(0xffffffffu, s, o);
    __shared__ float red[8];
    __shared__ float sv[256];
    if ((t & 31) == 0) red[t >> 5] = s;
    __syncthreads();
    if (t == 0) {
        float tot = 0.f;
        #pragma unroll
        for (int i = 0; i < 8; i++) tot += red[i];
        red[0] = fmaxf(sqrtf(tot), 1e-12f);
    }
    __syncthreads();
    sv[t] = v / red[0];
    __syncthreads();
    if (t < 32) {
        int cg = t;
        Pack8 u;
        #pragma unroll
        for (int i = 0; i < 8; i++) u.h[i] = __float2bfloat16(sv[cg * 8 + i]);
        int nc = n >> 7, r = n & 127, kc = cg >> 3;
        uint32_t off = r * 128 + (cg & 7) * 16;
        uint32_t sw = off ^ ((off >> 3) & 0x70);
        *(uint4*)(g_Bsw + ((size_t)(nc * 4 + kc)) * BLK + sw) = u.v;
    }
}

// ---------------------------------------------------------------------------
// One k64 step (EXACT R6 structure): 4x k16 {2 A ldmatrix, 4 B ldmatrix, 16 mma}.
// ---------------------------------------------------------------------------
__device__ __forceinline__ void kstep(uint32_t aBase, uint32_t bBase,
                                      float acc[2][8][4],
                                      int a_kbh, int b_rowoff, int b_kbh, int sx) {
    #pragma unroll
    for (int q = 0; q < 4; q++) {
        uint32_t a0[4], a1[4];
        uint32_t aAddr = aBase + ((q * 32 + a_kbh) ^ sx);
        LDSM_X4(a0[0], a0[1], a0[2], a0[3], aAddr);
        LDSM_X4(a1[0], a1[1], a1[2], a1[3], aAddr + 16 * 128);
        uint32_t bb[4][4];
        #pragma unroll
        for (int p = 0; p < 4; p++) {
            uint32_t bAddr = bBase + (p * 16 + b_rowoff) * 128 + ((q * 32 + b_kbh) ^ sx);
            LDSM_X4(bb[p][0], bb[p][1], bb[p][2], bb[p][3], bAddr);
        }
        #pragma unroll
        for (int nt = 0; nt < 8; nt++) {
            uint32_t bf0 = bb[nt >> 1][(nt & 1) * 2];
            uint32_t bf1 = bb[nt >> 1][(nt & 1) * 2 + 1];
            MMA_BF16(acc[0][nt], a0[0], a0[1], a0[2], a0[3], bf0, bf1);
            MMA_BF16(acc[1][nt], a1[0], a1[1], a1[2], a1[3], bf0, bf1);
        }
    }
}

// ---------------------------------------------------------------------------
// Kernel 3: HMMA GEMM (2 terms: hi_x.hi_e + lo_x.hi_e) + per-row top-2 per
// N-half. EXACT R6 mainloop/fold/merge; only the B-lo loop is deleted.
// 288 threads: warps 0-7 compute (4x2 warp grid, 32x64 tiles); warp 8 produces.
// ---------------------------------------------------------------------------
__global__ __launch_bounds__(288, 1) void mma_argmax_kernel() {
    extern __shared__ char smem[];
    const uint32_t sb = smem_u32(smem);
    uint4* sv2 = (uint4*)(smem + SM_SV2);
    const int tid = threadIdx.x, wid = tid >> 5, lane = tid & 31;

    if (tid == 0) {
        MBAR_INIT(sb + SM_AFULL, 1);
        #pragma unroll
        for (int s = 0; s < KST; s++) {
            MBAR_INIT(sb + SM_KFULL + 8 * s, 1);
            MBAR_INIT(sb + SM_KEMPTY + 8 * s, 8);
        }
        asm volatile("fence.proxy.async.shared::cta;" ::: "memory");
    }
    __syncthreads();

    if (wid == 8) {
        // ---- producer: A once (8 x 16KB), then B hi ring (4 blocks / tile) ----
        if (elect_one()) {
            MBAR_EXPECT_TX(sb + SM_AFULL, 8 * BLK);
            #pragma unroll
            for (int blk = 0; blk < 8; blk++)
                BULK_G2S(sb + SM_A + blk * BLK,
                         g_Asw + ((size_t)blockIdx.x * 8 + blk) * BLK,
                         BLK, sb + SM_AFULL);
            int ks = 0, kph = 1;
            for (int c = 0; c < NTILES; c++) {
                for (int t = 0; t < 4; t++) {
                    MBAR_WAIT(sb + SM_KEMPTY + 8 * ks, kph);
                    MBAR_EXPECT_TX(sb + SM_KFULL + 8 * ks, BLK);
                    BULK_G2S(sb + SM_B + ks * BLK,
                             g_Bsw + ((size_t)c * 4 + t) * BLK,
                             BLK, sb + SM_KFULL + 8 * ks);
                    if (++ks == KST) { ks = 0; kph ^= 1; }
                }
            }
        }
    } else {
        // ---- compute warps ----
        const int wm = wid >> 1, wn = wid & 1;
        const int sx = (lane & 7) * 16;
        const int a_row0 = lane & 15;
        const int a_kbh = (lane >> 4) * 16;
        const int b_rowoff = ((lane >> 4) & 1) * 8 + (lane & 7);
        const int b_kbh = ((lane >> 3) & 1) * 16;
        const uint32_t aWarp = sb + SM_A + wm * 4096 + a_row0 * 128;
        const int g = lane >> 2, cq = lane & 3;

        float tv1[4], tv2[4];
        int   ti1[4], ti2[4];
        #pragma unroll
        for (int s = 0; s < 4; s++) { tv1[s] = -3.4e38f; tv2[s] = -3.4e38f;
                                      ti1[s] = 0; ti2[s] = 0x7fffffff; }

        MBAR_WAIT(sb + SM_AFULL, 0);

        int ks = 0, kph = 0;
        for (int c = 0; c < NTILES; c++) {
            float acc[2][8][4];
            #pragma unroll
            for (int mt = 0; mt < 2; mt++)
                #pragma unroll
                for (int nt = 0; nt < 8; nt++)
                    #pragma unroll
                    for (int r = 0; r < 4; r++) acc[mt][nt][r] = 0.f;

            #pragma unroll 1
            for (int j = 0; j < 4; j++) {     // B hi_j: A = hi_j then lo_j
                MBAR_WAIT(sb + SM_KFULL + 8 * ks, kph);
                const uint32_t bBase = sb + SM_B + ks * BLK + wn * 8192;
                kstep(aWarp + j * BLK, bBase, acc, a_kbh, b_rowoff, b_kbh, sx);
                kstep(aWarp + (4 + j) * BLK, bBase, acc, a_kbh, b_rowoff, b_kbh, sx);
                if (lane == 0) MBAR_ARRIVE(sb + SM_KEMPTY + 8 * ks);
                if (++ks == KST) { ks = 0; kph ^= 1; }
            }

            // fold tile into running top-2 (EXACT R6 fold; ascending n per lane)
            #pragma unroll
            for (int mt = 0; mt < 2; mt++)
                #pragma unroll
                for (int half = 0; half < 2; half++) {
                    const int s = mt * 2 + half;
                    #pragma unroll
                    for (int nt = 0; nt < 8; nt++)
                        #pragma unroll
                        for (int jj = 0; jj < 2; jj++) {
                            float v = acc[mt][nt][half * 2 + jj];
                            int n = c * 128 + wn * 64 + nt * 8 + cq * 2 + jj;
                            if (v > tv1[s]) { tv2[s] = tv1[s]; ti2[s] = ti1[s];
                                              tv1[s] = v; ti1[s] = n; }
                            else if (v > tv2[s]) { tv2[s] = v; ti2[s] = n; }
                        }
                }
        }

        // quad reduction (lanes cq=0..3 share each row)
        #pragma unroll
        for (int o = 1; o <= 2; o <<= 1)
            #pragma unroll
            for (int s = 0; s < 4; s++) {
                float w1 = __shfl_xor_sync(0xffffffffu, tv1[s], o);
                float w2 = __shfl_xor_sync(0xffffffffu, tv2[s], o);
                int k1 = __shfl_xor_sync(0xffffffffu, ti1[s], o);
                int k2 = __shfl_xor_sync(0xffffffffu, ti2[s], o);
                merge_top2(tv1[s], ti1[s], tv2[s], ti2[s], w1, k1, w2, k2);
            }
        if (cq == 0) {
            #pragma unroll
            for (int s = 0; s < 4; s++) {
                int row = wm * 32 + (s >> 1) * 16 + (s & 1) * 8 + g;
                sv2[row * 2 + wn] = make_uint4(__float_as_uint(tv1[s]),
                                               (uint32_t)ti1[s],
                                               __float_as_uint(tv2[s]),
                                               (uint32_t)ti2[s]);
            }
        }
    }
    __syncthreads();
    if (tid < MT) {
        // candidates = top-2 of each N-half (disjoint partitions, 4 distinct)
        uint4 a = sv2[tid * 2], b = sv2[tid * 2 + 1];
        g_top4[blockIdx.x * MT + tid] =
            make_int4((int)a.y, (int)a.w, (int)b.y, (int)b.w);
    }
}

// ---------------------------------------------------------------------------
// Kernel 4: exact fp32 rescore of 4 candidates + projection/loss epilogue.
// One warp per row. Output: [x_q (B*D) | loss (1) | indices (B) | scalar (B)]
// ---------------------------------------------------------------------------
__global__ void epilogue_kernel(const float* __restrict__ X,
                                const float* __restrict__ E,
                                float* __restrict__ out) {
    const int gw   = (blockIdx.x * blockDim.x + threadIdx.x) >> 5;
    const int lane = threadIdx.x & 31;
    __shared__ float wsum[8];
    float contrib = 0.f;

    if (gw < B_) {
        const int b = gw;
        const int4 t4 = g_top4[b];
        const int cidx[4] = {t4.x, t4.y, t4.z, t4.w};
        const float4* xr = (const float4*)(X + (size_t)b * D_);
        float4 xv[2];
        float xsq = 0.f;
        #pragma unroll
        for (int r = 0; r < 2; r++) {
            xv[r] = xr[lane + r * 32];
            xsq += xv[r].x*xv[r].x + xv[r].y*xv[r].y + xv[r].z*xv[r].z + xv[r].w*xv[r].w;
        }
        float4 ev[4][2];
        float dots[4], nsqs[4];
        #pragma unroll
        for (int i = 0; i < 4; i++) {
            const float4* cr = (const float4*)(E + (size_t)cidx[i] * D_);
            float d = 0.f, nn = 0.f;
            #pragma unroll
            for (int r = 0; r < 2; r++) {
                ev[i][r] = cr[lane + r * 32];
                d  += xv[r].x*ev[i][r].x + xv[r].y*ev[i][r].y
                    + xv[r].z*ev[i][r].z + xv[r].w*ev[i][r].w;
                nn += ev[i][r].x*ev[i][r].x + ev[i][r].y*ev[i][r].y
                    + ev[i][r].z*ev[i][r].z + ev[i][r].w*ev[i][r].w;
            }
            dots[i] = d; nsqs[i] = nn;
        }
        #pragma unroll
        for (int o = 16; o; o >>= 1) {
            xsq += __shfl_xor_sync(0xffffffffu, xsq, o);
            #pragma unroll
            for (int i = 0; i < 4; i++) {
                dots[i] += __shfl_xor_sync(0xffffffffu, dots[i], o);
                nsqs[i] += __shfl_xor_sync(0xffffffffu, nsqs[i], o);
            }
        }
        // exact selection: argmax of x.e / max(||e||,eps), lowest index on tie
        int   bidx = cidx[0];
        float bs   = dots[0] / fmaxf(sqrtf(nsqs[0]), 1e-12f);
        float bdot = dots[0], bnsq = nsqs[0];
        int   bsel = 0;
        #pragma unroll
        for (int i = 1; i < 4; i++) {
            float si = dots[i] / fmaxf(sqrtf(nsqs[i]), 1e-12f);
            if (si > bs || (si == bs && cidx[i] < bidx)) {
                bs = si; bidx = cidx[i]; bdot = dots[i]; bnsq = nsqs[i]; bsel = i;
            }
        }
        const float scalar = bdot / (bnsq + 1e-8f);

        float4* orow = (float4*)(out + (size_t)b * D_);
        #pragma unroll
        for (int r = 0; r < 2; r++) {
            float4 cv = ev[0][r];
            if (bsel == 1) cv = ev[1][r];
            else if (bsel == 2) cv = ev[2][r];
            else if (bsel == 3) cv = ev[3][r];
            float4 o;
            o.x = xv[r].x + (scalar * cv.x - xv[r].x);
            o.y = xv[r].y + (scalar * cv.y - xv[r].y);
            o.z = xv[r].z + (scalar * cv.z - xv[r].z);
            o.w = xv[r].w + (scalar * cv.w - xv[r].w);
            orow[lane + r * 32] = o;
        }
        if (lane == 0) {
            out[(size_t)B_ * D_ + 1 + b]      = (float)bidx;
            out[(size_t)B_ * D_ + 1 + B_ + b] = scalar;
            const float nproj = fabsf(scalar) * sqrtf(bnsq);
            const float nx = sqrtf(xsq);
            const float commit = (scalar * bdot) /
                (fmaxf(nproj, 1e-8f) * fmaxf(nx, 1e-8f));
            contrib = 1.f - commit;
        }
    }
    const int w = threadIdx.x >> 5;
    if (lane == 0) wsum[w] = contrib;
    __syncthreads();
    if (threadIdx.x == 0) {
        float s = 0.f;
        #pragma unroll
        for (int i = 0; i < 8; i++) s += wsum[i];
        g_partial[blockIdx.x] = s;
    }
}

// ---------------------------------------------------------------------------
// Kernel 5: deterministic final loss reduction.
// ---------------------------------------------------------------------------
__global__ void loss_kernel(float* __restrict__ out) {
    __shared__ double red[256];
    const int t = threadIdx.x;
    double s = 0.0;
    for (int i = t; i < EPI_BLOCKS; i += 256) s += (double)g_partial[i];
    red[t] = s;
    __syncthreads();
    for (int o = 128; o; o >>= 1) {
        if (t < o) red[t] += red[t + o];
        __syncthreads();
    }
    if (t == 0) out[(size_t)B_ * D_] = (float)(0.25 * red[0] / (double)B_);
}

// ---------------------------------------------------------------------------
extern "C" void kernel_launch(void* const* d_in, const int* in_sizes, int n_in,
                              void* d_out, int out_size) {
    const float* X = (const float*)d_in[0];   // (32768, 256) fp32
    const float* E = (const float*)d_in[1];   // (8192, 256) fp32
    float* out = (float*)d_out;

    cudaFuncSetAttribute(mma_argmax_kernel,
                         cudaFuncAttributeMaxDynamicSharedMemorySize, SMEM_TOTAL);

    split_x_kernel<<<B_ * 32 / 256, 256>>>(X);
    split_cb_kernel<<<N_, 256>>>(E);
    mma_argmax_kernel<<<MTILES, 288, SMEM_TOTAL>>>();
    epilogue_kernel<<<EPI_BLOCKS, 256>>>(X, E, out);
    loss_kernel<<<1, 256>>>(out);
}

// round 10
// speedup vs baseline: 3.6982x; 1.4860x over previous
#include <cuda_runtime.h>
#include <cuda_fp16.h>
#include <math.h>
#include <stdint.h>

// ---------------------------------------------------------------------------
// Problem constants
// ---------------------------------------------------------------------------
#define B_ 32768
#define D_ 256
#define N_ 8192

#define MT 128              // M rows per CTA
#define NTILE 128           // N cols per B stream block
#define NTILES (N_ / NTILE) // 64
#define MTILES (B_ / MT)    // 256
#define KST 4               // B smem ring stages

#define BLK 16384           // one k64 block: 128 rows x 64 fp16 (SW128-swizzled)

// dynamic smem layout
#define SM_AFULL  8
#define SM_KFULL  16        // 4 x 8B  (16..47)
#define SM_KEMPTY 48        // 4 x 8B  (48..79)
#define SM_SV2    128       // uint4[128][2] = 4KB
#define SM_A      8192      // 4 x 16KB = 64KB (x fp16, k0-3)
#define SM_B      (SM_A + 4 * BLK)       // 73728
#define SMEM_TOTAL (SM_B + KST * BLK)    // 139264

#define EPI_BLOCKS (B_ / 8)

// ---------------------------------------------------------------------------
// Global scratch
// ---------------------------------------------------------------------------
__device__ __align__(16) uint8_t g_Asw[(size_t)MTILES * 4 * BLK];  // 16 MB
__device__ __align__(16) uint8_t g_Bsw[(size_t)NTILES * 4 * BLK];  // 4 MB
__device__ int4  g_top4[B_];
__device__ float g_partial[EPI_BLOCKS];

// ---------------------------------------------------------------------------
// PTX helpers (family-wide features only — NO tcgen05 at compute_103)
// ---------------------------------------------------------------------------
__device__ __forceinline__ uint32_t smem_u32(const void* p) {
    uint32_t a;
    asm("{ .reg .u64 t; cvta.to.shared.u64 t, %1; cvt.u32.u64 %0, t; }"
        : "=r"(a) : "l"(p));
    return a;
}
__device__ __forceinline__ uint32_t elect_one() {
    uint32_t pred;
    asm volatile("{\n\t.reg .pred p;\n\telect.sync _|p, 0xFFFFFFFF;\n\t"
                 "selp.b32 %0, 1, 0, p;\n\t}" : "=r"(pred));
    return pred;
}
#define MBAR_INIT(addr, cnt) \
    asm volatile("mbarrier.init.shared.b64 [%0], %1;" :: "r"(addr), "r"(cnt) : "memory")
#define MBAR_EXPECT_TX(addr, bytes) \
    asm volatile("mbarrier.arrive.expect_tx.shared.b64 _, [%0], %1;" \
                 :: "r"(addr), "r"(bytes) : "memory")
#define MBAR_ARRIVE(addr) \
    asm volatile("mbarrier.arrive.shared.b64 _, [%0];" :: "r"(addr) : "memory")
#define MBAR_WAIT(addr, ph) do {                                              \
    uint32_t _m = (addr), _p = (ph), _d;                                      \
    asm volatile("{\n\t.reg .pred p;\n\t"                                     \
        "mbarrier.try_wait.parity.acquire.cta.shared::cta.b64 p, [%1], %2;\n\t" \
        "selp.b32 %0, 1, 0, p;\n\t}" : "=r"(_d) : "r"(_m), "r"(_p) : "memory");\
    if (!_d) {                                                                \
        asm volatile("{\n\t.reg .pred P1;\n\t"                                \
            "WL_%=:\n\t"                                                      \
            "mbarrier.try_wait.parity.acquire.cta.shared::cta.b64 P1, [%0], %1, 0x989680;\n\t" \
            "@P1 bra.uni WD_%=;\n\t"                                          \
            "bra.uni WL_%=;\n\t"                                              \
            "WD_%=:\n\t}" :: "r"(_m), "r"(_p) : "memory");                    \
    } } while (0)
#define BULK_G2S(dst, src, bytes, mbar) \
    asm volatile("cp.async.bulk.shared::cta.global.mbarrier::complete_tx::bytes " \
                 "[%0], [%1], %2, [%3];" \
                 :: "r"(dst), "l"(src), "r"(bytes), "r"(mbar) : "memory")
#define LDSM_X4(r0, r1, r2, r3, a) \
    asm volatile("ldmatrix.sync.aligned.m8n8.x4.shared.b16 {%0,%1,%2,%3}, [%4];" \
        : "=r"(r0), "=r"(r1), "=r"(r2), "=r"(r3) : "r"(a))
#define MMA_F16(d, a0, a1, a2, a3, b0, b1) \
    asm volatile("mma.sync.aligned.m16n8k16.row.col.f32.f16.f16.f32 " \
        "{%0,%1,%2,%3}, {%4,%5,%6,%7}, {%8,%9}, {%0,%1,%2,%3};" \
        : "+f"((d)[0]), "+f"((d)[1]), "+f"((d)[2]), "+f"((d)[3]) \
        : "r"(a0), "r"(a1), "r"(a2), "r"(a3), "r"(b0), "r"(b1))

union Pack8 { __half h[8]; uint4 v; };

__device__ __forceinline__ void merge_top2(float& v1, int& i1, float& v2, int& i2,
                                           float w1, int k1, float w2, int k2) {
    if (w1 > v1 || (w1 == v1 && k1 < i1)) {
        if (v1 > w2 || (v1 == w2 && i1 < k2)) { v2 = v1; i2 = i1; }
        else                                   { v2 = w2; i2 = k2; }
        v1 = w1; i1 = k1;
    } else if (w1 > v2 || (w1 == v2 && k1 < i2)) {
        v2 = w1; i2 = k1;
    }
}

// ---------------------------------------------------------------------------
// Kernel 1: convert X to fp16, pre-swizzled SW128 16KB blocks.
// Block (mtile*4 + kc); element (m, col) at swizzle(m*128 + col*2).
// ---------------------------------------------------------------------------
__global__ void split_x_kernel(const float* __restrict__ X) {
    int g = blockIdx.x * 256 + threadIdx.x;
    int b  = g >> 5;
    int cg = g & 31;
    const float4* xp = (const float4*)(X + (size_t)b * D_ + cg * 8);
    float4 x0 = xp[0], x1 = xp[1];
    float xs[8] = {x0.x, x0.y, x0.z, x0.w, x1.x, x1.y, x1.z, x1.w};
    Pack8 u;
    #pragma unroll
    for (int i = 0; i < 8; i++) u.h[i] = __float2half(xs[i]);
    int mtile = b >> 7, m = b & 127, kc = cg >> 3;
    uint32_t off = m * 128 + (cg & 7) * 16;
    uint32_t sw = off ^ ((off >> 3) & 0x70);
    *(uint4*)(g_Asw + ((size_t)(mtile * 4 + kc)) * BLK + sw) = u.v;
}

// ---------------------------------------------------------------------------
// Kernel 2: normalize codebook rows, fp16, pre-swizzled blocks.
// ---------------------------------------------------------------------------
__global__ void split_cb_kernel(const float* __restrict__ E) {
    int n = blockIdx.x;
    int t = threadIdx.x;
    float v = E[(size_t)n * D_ + t];
    float s = v * v;
    #pragma unroll
    for (int o = 16; o; o >>= 1) s += __shfl_xor_sync(0xffffffffu, s, o);
    __shared__ float red[8];
    __shared__ float sv[256];
    if ((t & 31) == 0) red[t >> 5] = s;
    __syncthreads();
    if (t == 0) {
        float tot = 0.f;
        #pragma unroll
        for (int i = 0; i < 8; i++) tot += red[i];
        red[0] = fmaxf(sqrtf(tot), 1e-12f);
    }
    __syncthreads();
    sv[t] = v / red[0];
    __syncthreads();
    if (t < 32) {
        int cg = t;
        Pack8 u;
        #pragma unroll
        for (int i = 0; i < 8; i++) u.h[i] = __float2half(sv[cg * 8 + i]);
        int nc = n >> 7, r = n & 127, kc = cg >> 3;
        uint32_t off = r * 128 + (cg & 7) * 16;
        uint32_t sw = off ^ ((off >> 3) & 0x70);
        *(uint4*)(g_Bsw + ((size_t)(nc * 4 + kc)) * BLK + sw) = u.v;
    }
}

// ---------------------------------------------------------------------------
// One k64 step (EXACT R6/R9 structure): 4x k16 {2 A ldmatrix, 4 B ldmatrix, 16 mma}.
// ---------------------------------------------------------------------------
__device__ __forceinline__ void kstep(uint32_t aBase, uint32_t bBase,
                                      float acc[2][8][4],
                                      int a_kbh, int b_rowoff, int b_kbh, int sx) {
    #pragma unroll
    for (int q = 0; q < 4; q++) {
        uint32_t a0[4], a1[4];
        uint32_t aAddr = aBase + ((q * 32 + a_kbh) ^ sx);
        LDSM_X4(a0[0], a0[1], a0[2], a0[3], aAddr);
        LDSM_X4(a1[0], a1[1], a1[2], a1[3], aAddr + 16 * 128);
        uint32_t bb[4][4];
        #pragma unroll
        for (int p = 0; p < 4; p++) {
            uint32_t bAddr = bBase + (p * 16 + b_rowoff) * 128 + ((q * 32 + b_kbh) ^ sx);
            LDSM_X4(bb[p][0], bb[p][1], bb[p][2], bb[p][3], bAddr);
        }
        #pragma unroll
        for (int nt = 0; nt < 8; nt++) {
            uint32_t bf0 = bb[nt >> 1][(nt & 1) * 2];
            uint32_t bf1 = bb[nt >> 1][(nt & 1) * 2 + 1];
            MMA_F16(acc[0][nt], a0[0], a0[1], a0[2], a0[3], bf0, bf1);
            MMA_F16(acc[1][nt], a1[0], a1[1], a1[2], a1[3], bf0, bf1);
        }
    }
}

// ---------------------------------------------------------------------------
// Kernel 3: fp16 HMMA GEMM (single term) + per-row top-2 per N-half.
// EXACT R9 mainloop/fold/merge; one kstep per B block instead of two.
// 288 threads: warps 0-7 compute (4x2 warp grid, 32x64 tiles); warp 8 produces.
// ---------------------------------------------------------------------------
__global__ __launch_bounds__(288, 1) void mma_argmax_kernel() {
    extern __shared__ char smem[];
    const uint32_t sb = smem_u32(smem);
    uint4* sv2 = (uint4*)(smem + SM_SV2);
    const int tid = threadIdx.x, wid = tid >> 5, lane = tid & 31;

    if (tid == 0) {
        MBAR_INIT(sb + SM_AFULL, 1);
        #pragma unroll
        for (int s = 0; s < KST; s++) {
            MBAR_INIT(sb + SM_KFULL + 8 * s, 1);
            MBAR_INIT(sb + SM_KEMPTY + 8 * s, 8);
        }
        asm volatile("fence.proxy.async.shared::cta;" ::: "memory");
    }
    __syncthreads();

    if (wid == 8) {
        // ---- producer: A once (4 x 16KB), then B ring (4 blocks / tile) ----
        if (elect_one()) {
            MBAR_EXPECT_TX(sb + SM_AFULL, 4 * BLK);
            #pragma unroll
            for (int blk = 0; blk < 4; blk++)
                BULK_G2S(sb + SM_A + blk * BLK,
                         g_Asw + ((size_t)blockIdx.x * 4 + blk) * BLK,
                         BLK, sb + SM_AFULL);
            int ks = 0, kph = 1;
            for (int c = 0; c < NTILES; c++) {
                for (int t = 0; t < 4; t++) {
                    MBAR_WAIT(sb + SM_KEMPTY + 8 * ks, kph);
                    MBAR_EXPECT_TX(sb + SM_KFULL + 8 * ks, BLK);
                    BULK_G2S(sb + SM_B + ks * BLK,
                             g_Bsw + ((size_t)c * 4 + t) * BLK,
                             BLK, sb + SM_KFULL + 8 * ks);
                    if (++ks == KST) { ks = 0; kph ^= 1; }
                }
            }
        }
    } else {
        // ---- compute warps ----
        const int wm = wid >> 1, wn = wid & 1;
        const int sx = (lane & 7) * 16;
        const int a_row0 = lane & 15;
        const int a_kbh = (lane >> 4) * 16;
        const int b_rowoff = ((lane >> 4) & 1) * 8 + (lane & 7);
        const int b_kbh = ((lane >> 3) & 1) * 16;
        const uint32_t aWarp = sb + SM_A + wm * 4096 + a_row0 * 128;
        const int g = lane >> 2, cq = lane & 3;

        float tv1[4], tv2[4];
        int   ti1[4], ti2[4];
        #pragma unroll
        for (int s = 0; s < 4; s++) { tv1[s] = -3.4e38f; tv2[s] = -3.4e38f;
                                      ti1[s] = 0; ti2[s] = 0x7fffffff; }

        MBAR_WAIT(sb + SM_AFULL, 0);

        int ks = 0, kph = 0;
        for (int c = 0; c < NTILES; c++) {
            float acc[2][8][4];
            #pragma unroll
            for (int mt = 0; mt < 2; mt++)
                #pragma unroll
                for (int nt = 0; nt < 8; nt++)
                    #pragma unroll
                    for (int r = 0; r < 4; r++) acc[mt][nt][r] = 0.f;

            #pragma unroll 1
            for (int j = 0; j < 4; j++) {     // B_j against A_j (single term)
                MBAR_WAIT(sb + SM_KFULL + 8 * ks, kph);
                const uint32_t bBase = sb + SM_B + ks * BLK + wn * 8192;
                kstep(aWarp + j * BLK, bBase, acc, a_kbh, b_rowoff, b_kbh, sx);
                if (lane == 0) MBAR_ARRIVE(sb + SM_KEMPTY + 8 * ks);
                if (++ks == KST) { ks = 0; kph ^= 1; }
            }

            // fold tile into running top-2 (EXACT R6 fold; ascending n per lane)
            #pragma unroll
            for (int mt = 0; mt < 2; mt++)
                #pragma unroll
                for (int half = 0; half < 2; half++) {
                    const int s = mt * 2 + half;
                    #pragma unroll
                    for (int nt = 0; nt < 8; nt++)
                        #pragma unroll
                        for (int jj = 0; jj < 2; jj++) {
                            float v = acc[mt][nt][half * 2 + jj];
                            int n = c * 128 + wn * 64 + nt * 8 + cq * 2 + jj;
                            if (v > tv1[s]) { tv2[s] = tv1[s]; ti2[s] = ti1[s];
                                              tv1[s] = v; ti1[s] = n; }
                            else if (v > tv2[s]) { tv2[s] = v; ti2[s] = n; }
                        }
                }
        }

        // quad reduction (lanes cq=0..3 share each row)
        #pragma unroll
        for (int o = 1; o <= 2; o <<= 1)
            #pragma unroll
            for (int s = 0; s < 4; s++) {
                float w1 = __shfl_xor_sync(0xffffffffu, tv1[s], o);
                float w2 = __shfl_xor_sync(0xffffffffu, tv2[s], o);
                int k1 = __shfl_xor_sync(0xffffffffu, ti1[s], o);
                int k2 = __shfl_xor_sync(0xffffffffu, ti2[s], o);
                merge_top2(tv1[s], ti1[s], tv2[s], ti2[s], w1, k1, w2, k2);
            }
        if (cq == 0) {
            #pragma unroll
            for (int s = 0; s < 4; s++) {
                int row = wm * 32 + (s >> 1) * 16 + (s & 1) * 8 + g;
                sv2[row * 2 + wn] = make_uint4(__float_as_uint(tv1[s]),
                                               (uint32_t)ti1[s],
                                               __float_as_uint(tv2[s]),
                                               (uint32_t)ti2[s]);
            }
        }
    }
    __syncthreads();
    if (tid < MT) {
        // candidates = top-2 of each N-half (disjoint partitions, 4 distinct)
        uint4 a = sv2[tid * 2], b = sv2[tid * 2 + 1];
        g_top4[blockIdx.x * MT + tid] =
            make_int4((int)a.y, (int)a.w, (int)b.y, (int)b.w);
    }
}

// ---------------------------------------------------------------------------
// Kernel 4: exact fp32 rescore of 4 candidates + projection/loss epilogue.
// One warp per row. Output: [x_q (B*D) | loss (1) | indices (B) | scalar (B)]
// ---------------------------------------------------------------------------
__global__ void epilogue_kernel(const float* __restrict__ X,
                                const float* __restrict__ E,
                                float* __restrict__ out) {
    const int gw   = (blockIdx.x * blockDim.x + threadIdx.x) >> 5;
    const int lane = threadIdx.x & 31;
    __shared__ float wsum[8];
    float contrib = 0.f;

    if (gw < B_) {
        const int b = gw;
        const int4 t4 = g_top4[b];
        const int cidx[4] = {t4.x, t4.y, t4.z, t4.w};
        const float4* xr = (const float4*)(X + (size_t)b * D_);
        float4 xv[2];
        float xsq = 0.f;
        #pragma unroll
        for (int r = 0; r < 2; r++) {
            xv[r] = xr[lane + r * 32];
            xsq += xv[r].x*xv[r].x + xv[r].y*xv[r].y + xv[r].z*xv[r].z + xv[r].w*xv[r].w;
        }
        float4 ev[4][2];
        float dots[4], nsqs[4];
        #pragma unroll
        for (int i = 0; i < 4; i++) {
            const float4* cr = (const float4*)(E + (size_t)cidx[i] * D_);
            float d = 0.f, nn = 0.f;
            #pragma unroll
            for (int r = 0; r < 2; r++) {
                ev[i][r] = cr[lane + r * 32];
                d  += xv[r].x*ev[i][r].x + xv[r].y*ev[i][r].y
                    + xv[r].z*ev[i][r].z + xv[r].w*ev[i][r].w;
                nn += ev[i][r].x*ev[i][r].x + ev[i][r].y*ev[i][r].y
                    + ev[i][r].z*ev[i][r].z + ev[i][r].w*ev[i][r].w;
            }
            dots[i] = d; nsqs[i] = nn;
        }
        #pragma unroll
        for (int o = 16; o; o >>= 1) {
            xsq += __shfl_xor_sync(0xffffffffu, xsq, o);
            #pragma unroll
            for (int i = 0; i < 4; i++) {
                dots[i] += __shfl_xor_sync(0xffffffffu, dots[i], o);
                nsqs[i] += __shfl_xor_sync(0xffffffffu, nsqs[i], o);
            }
        }
        // exact selection: argmax of x.e / max(||e||,eps), lowest index on tie
        int   bidx = cidx[0];
        float bs   = dots[0] / fmaxf(sqrtf(nsqs[0]), 1e-12f);
        float bdot = dots[0], bnsq = nsqs[0];
        int   bsel = 0;
        #pragma unroll
        for (int i = 1; i < 4; i++) {
            float si = dots[i] / fmaxf(sqrtf(nsqs[i]), 1e-12f);
            if (si > bs || (si == bs && cidx[i] < bidx)) {
                bs = si; bidx = cidx[i]; bdot = dots[i]; bnsq = nsqs[i]; bsel = i;
            }
        }
        const float scalar = bdot / (bnsq + 1e-8f);

        float4* orow = (float4*)(out + (size_t)b * D_);
        #pragma unroll
        for (int r = 0; r < 2; r++) {
            float4 cv = ev[0][r];
            if (bsel == 1) cv = ev[1][r];
            else if (bsel == 2) cv = ev[2][r];
            else if (bsel == 3) cv = ev[3][r];
            float4 o;
            o.x = xv[r].x + (scalar * cv.x - xv[r].x);
            o.y = xv[r].y + (scalar * cv.y - xv[r].y);
            o.z = xv[r].z + (scalar * cv.z - xv[r].z);
            o.w = xv[r].w + (scalar * cv.w - xv[r].w);
            orow[lane + r * 32] = o;
        }
        if (lane == 0) {
            out[(size_t)B_ * D_ + 1 + b]      = (float)bidx;
            out[(size_t)B_ * D_ + 1 + B_ + b] = scalar;
            const float nproj = fabsf(scalar) * sqrtf(bnsq);
            const float nx = sqrtf(xsq);
            const float commit = (scalar * bdot) /
                (fmaxf(nproj, 1e-8f) * fmaxf(nx, 1e-8f));
            contrib = 1.f - commit;
        }
    }
    const int w = threadIdx.x >> 5;
    if (lane == 0) wsum[w] = contrib;
    __syncthreads();
    if (threadIdx.x == 0) {
        float s = 0.f;
        #pragma unroll
        for (int i = 0; i < 8; i++) s += wsum[i];
        g_partial[blockIdx.x] = s;
    }
}

// ---------------------------------------------------------------------------
// Kernel 5: deterministic final loss reduction.
// ---------------------------------------------------------------------------
__global__ void loss_kernel(float* __restrict__ out) {
    __shared__ double red[256];
    const int t = threadIdx.x;
    double s = 0.0;
    for (int i = t; i < EPI_BLOCKS; i += 256) s += (double)g_partial[i];
    red[t] = s;
    __syncthreads();
    for (int o = 128; o; o >>= 1) {
        if (t < o) red[t] += red[t + o];
        __syncthreads();
    }
    if (t == 0) out[(size_t)B_ * D_] = (float)(0.25 * red[0] / (double)B_);
}

// ---------------------------------------------------------------------------
extern "C" void kernel_launch(void* const* d_in, const int* in_sizes, int n_in,
                              void* d_out, int out_size) {
    const float* X = (const float*)d_in[0];   // (32768, 256) fp32
    const float* E = (const float*)d_in[1];   // (8192, 256) fp32
    float* out = (float*)d_out;

    cudaFuncSetAttribute(mma_argmax_kernel,
                         cudaFuncAttributeMaxDynamicSharedMemorySize, SMEM_TOTAL);

    split_x_kernel<<<B_ * 32 / 256, 256>>>(X);
    split_cb_kernel<<<N_, 256>>>(E);
    mma_argmax_kernel<<<MTILES, 288, SMEM_TOTAL>>>();
    epilogue_kernel<<<EPI_BLOCKS, 256>>>(X, E, out);
    loss_kernel<<<1, 256>>>(out);
}